// round 1
// baseline (speedup 1.0000x reference)
#include <cuda_runtime.h>

// ---------------------------------------------------------------------------
// DCGN: normalized adjacency is provably the identity matrix (diagonal A,
// symmetric normalization => diag of ones). Network reduces to:
//   g1 = node_conv(x, conv1_w)                [8192, 2048]
//   h  = lrelu(g1 @ prop1_W + prop1_B)        [8192, 1100]
//   g2 = node_conv(h, conv2_w)                [2048, 1100]
//   out= lrelu(g2 @ prop2_W + prop2_B)        [2048, 512]
// ---------------------------------------------------------------------------

#define ROWS1 8192   // 64 * 128
#define ROWS2 2048   // 64 * 32
#define F1    2048
#define F2    1100
#define NCLS  512

__device__ float g_g1[(size_t)ROWS1 * F1];   // 64 MB
__device__ float g_h [(size_t)ROWS1 * F2];   // 36 MB
__device__ float g_g2[(size_t)ROWS2 * F2];   //  9 MB

// out[r, f] = sum_{p<4} x[(4r+p), f] * w[p, f]   (vectorized over f by 4)
__global__ void nodeconv4(const float* __restrict__ x,
                          const float* __restrict__ w,
                          float* __restrict__ out,
                          int rows, int F4)
{
    int idx = blockIdx.x * blockDim.x + threadIdx.x;
    if (idx >= rows * F4) return;
    int r = idx / F4;
    int c = idx - r * F4;
    const float4* x4 = (const float4*)x;
    const float4* w4 = (const float4*)w;
    float4 acc = make_float4(0.f, 0.f, 0.f, 0.f);
#pragma unroll
    for (int p = 0; p < 4; ++p) {
        float4 xv = x4[(size_t)(4 * r + p) * F4 + c];
        float4 wv = w4[p * F4 + c];
        acc.x = fmaf(xv.x, wv.x, acc.x);
        acc.y = fmaf(xv.y, wv.y, acc.y);
        acc.z = fmaf(xv.z, wv.z, acc.z);
        acc.w = fmaf(xv.w, wv.w, acc.w);
    }
    ((float4*)out)[(size_t)r * F4 + c] = acc;
}

// C[M,N] = lrelu(A[M,K] @ B[K,N] + bias[N])
// Classic 128x128x8 SIMT SGEMM, 256 threads, 8x8 per thread.
// M must be a multiple of 128 (true here: 8192 and 2048). N, K arbitrary.
#define BM 128
#define BN 128
#define BK 8

__global__ __launch_bounds__(256, 2)
void sgemm_bias_lrelu(const float* __restrict__ A,
                      const float* __restrict__ Bm,
                      const float* __restrict__ bias,
                      float* __restrict__ C,
                      int M, int N, int K)
{
    __shared__ float As[BK][BM];
    __shared__ float Bs[BK][BN];

    const int tid  = threadIdx.x;
    const int row0 = blockIdx.y * BM;
    const int col0 = blockIdx.x * BN;
    const int tx = tid & 15;   // 0..15 -> col groups of 8
    const int ty = tid >> 4;   // 0..15 -> row groups of 8

    float acc[8][8];
#pragma unroll
    for (int i = 0; i < 8; ++i)
#pragma unroll
        for (int j = 0; j < 8; ++j) acc[i][j] = 0.f;

    // A-tile load mapping: 128 rows x 8 k, one float4 per thread
    const int a_row = tid >> 1;
    const int a_k   = (tid & 1) * 4;
    // B-tile load mapping: 8 k x 128 cols, one float4 per thread
    const int b_k   = tid >> 5;
    const int b_col = (tid & 31) * 4;

    for (int k0 = 0; k0 < K; k0 += BK) {
        // ---- load A tile (rows always in-bounds; guard K) ----
        float4 av;
        const float* Ap = A + (size_t)(row0 + a_row) * K + (k0 + a_k);
        if (k0 + a_k + 3 < K) {
            av = *(const float4*)Ap;
        } else {
            av.x = (k0 + a_k + 0 < K) ? Ap[0] : 0.f;
            av.y = (k0 + a_k + 1 < K) ? Ap[1] : 0.f;
            av.z = (k0 + a_k + 2 < K) ? Ap[2] : 0.f;
            av.w = (k0 + a_k + 3 < K) ? Ap[3] : 0.f;
        }
        As[a_k + 0][a_row] = av.x;
        As[a_k + 1][a_row] = av.y;
        As[a_k + 2][a_row] = av.z;
        As[a_k + 3][a_row] = av.w;

        // ---- load B tile (guard K and N) ----
        float4 bv = make_float4(0.f, 0.f, 0.f, 0.f);
        if (k0 + b_k < K) {
            const int c = col0 + b_col;
            const float* Bp = Bm + (size_t)(k0 + b_k) * N + c;
            if (c + 3 < N) {
                bv = *(const float4*)Bp;
            } else {
                if (c + 0 < N) bv.x = Bp[0];
                if (c + 1 < N) bv.y = Bp[1];
                if (c + 2 < N) bv.z = Bp[2];
                if (c + 3 < N) bv.w = Bp[3];
            }
        }
        *(float4*)&Bs[b_k][b_col] = bv;

        __syncthreads();

#pragma unroll
        for (int k = 0; k < BK; ++k) {
            float ar[8], br[8];
#pragma unroll
            for (int i = 0; i < 8; ++i) ar[i] = As[k][ty * 8 + i];
#pragma unroll
            for (int j = 0; j < 8; ++j) br[j] = Bs[k][tx * 8 + j];
#pragma unroll
            for (int i = 0; i < 8; ++i)
#pragma unroll
                for (int j = 0; j < 8; ++j)
                    acc[i][j] = fmaf(ar[i], br[j], acc[i][j]);
        }
        __syncthreads();
    }

    // ---- epilogue: bias + leaky relu ----
#pragma unroll
    for (int i = 0; i < 8; ++i) {
        const int r = row0 + ty * 8 + i;
#pragma unroll
        for (int j = 0; j < 8; ++j) {
            const int c = col0 + tx * 8 + j;
            if (c < N) {
                float v = acc[i][j] + __ldg(&bias[c]);
                C[(size_t)r * N + c] = (v >= 0.f) ? v : 0.01f * v;
            }
        }
    }
}

extern "C" void kernel_launch(void* const* d_in, const int* in_sizes, int n_in,
                              void* d_out, int out_size)
{
    const float* x       = (const float*)d_in[0];   // [64,512,2048]
    const float* conv1_w = (const float*)d_in[1];   // [4,2048]
    // d_in[2], d_in[3]: pool1_w / pool1_b -> dead (adjacency == identity)
    const float* prop1_W = (const float*)d_in[4];   // [2048,1100]
    const float* prop1_B = (const float*)d_in[5];   // [1100]
    const float* conv2_w = (const float*)d_in[6];   // [4,1100]
    // d_in[7], d_in[8]: pool2_w / pool2_b -> dead
    const float* prop2_W = (const float*)d_in[9];   // [1100,512]
    const float* prop2_B = (const float*)d_in[10];  // [512]

    float* g1; cudaGetSymbolAddress((void**)&g1, g_g1);
    float* h;  cudaGetSymbolAddress((void**)&h,  g_h);
    float* g2; cudaGetSymbolAddress((void**)&g2, g_g2);
    float* out = (float*)d_out;

    // 1) g1 = node_conv(x, conv1_w):  [8192, 2048]
    {
        int total = ROWS1 * (F1 / 4);
        nodeconv4<<<(total + 255) / 256, 256>>>(x, conv1_w, g1, ROWS1, F1 / 4);
    }

    // 2) h = lrelu(g1 @ prop1_W + prop1_B):  [8192, 1100]
    {
        dim3 grid((F2 + BN - 1) / BN, ROWS1 / BM);  // (9, 64)
        sgemm_bias_lrelu<<<grid, 256>>>(g1, prop1_W, prop1_B, h, ROWS1, F2, F1);
    }

    // 3) g2 = node_conv(h, conv2_w):  [2048, 1100]
    {
        int total = ROWS2 * (F2 / 4);
        nodeconv4<<<(total + 255) / 256, 256>>>(h, conv2_w, g2, ROWS2, F2 / 4);
    }

    // 4) out = lrelu(g2 @ prop2_W + prop2_B):  [2048, 512]
    {
        dim3 grid((NCLS + BN - 1) / BN, ROWS2 / BM); // (4, 16)
        sgemm_bias_lrelu<<<grid, 256>>>(g2, prop2_W, prop2_B, out, ROWS2, NCLS, F2);
    }
}

// round 3
// speedup vs baseline: 2.9552x; 2.9552x over previous
#include <cuda_runtime.h>
#include <cuda_bf16.h>
#include <cstdint>

// ---------------------------------------------------------------------------
// DCGN collapses (normalized adjacency == identity) to:
//   g1 = node_conv(x, conv1_w)                [8192, 2048]
//   h  = lrelu(g1 @ prop1_W + prop1_B)        [8192, 1100]  (N pad -> 1152)
//   g2 = node_conv(h, conv2_w)                [2048, 1100]  (K pad -> 1152)
//   out= lrelu(g2 @ prop2_W + prop2_B)        [2048, 512]
// GEMMs: bf16x3 split (AhiBhi + AhiBlo + AloBhi) on mma.sync.m16n8k16
// (tcgen05 is unavailable: harness PTX targets sm_103 without the 'a' suffix)
// ---------------------------------------------------------------------------

#define ROWS1 8192
#define F1    2048
#define N1R   1100
#define N1P   1152
#define ROWS2 2048
#define K2P   1152
#define N2    512

__device__ __nv_bfloat16 g_g1hi[(size_t)ROWS1 * F1];
__device__ __nv_bfloat16 g_g1lo[(size_t)ROWS1 * F1];
__device__ float         g_h   [(size_t)ROWS1 * N1P];
__device__ __nv_bfloat16 g_g2hi[(size_t)ROWS2 * K2P];
__device__ __nv_bfloat16 g_g2lo[(size_t)ROWS2 * K2P];
__device__ __nv_bfloat16 g_w1hi[(size_t)N1P * F1];
__device__ __nv_bfloat16 g_w1lo[(size_t)N1P * F1];
__device__ __nv_bfloat16 g_w2hi[(size_t)N2 * K2P];
__device__ __nv_bfloat16 g_w2lo[(size_t)N2 * K2P];

// ===================== PTX helpers ========================

__device__ __forceinline__ uint32_t smem_u32(const void* p) {
    uint32_t a;
    asm("{ .reg .u64 t; cvta.to.shared.u64 t, %1; cvt.u32.u64 %0, t; }"
        : "=r"(a) : "l"(p));
    return a;
}

__device__ __forceinline__ void cp16(uint32_t dst, const void* src) {
    asm volatile("cp.async.cg.shared.global [%0], [%1], 16;"
                 :: "r"(dst), "l"(src));
}

__device__ __forceinline__ void ldm_x4(uint32_t* r, uint32_t addr) {
    asm volatile("ldmatrix.sync.aligned.m8n8.x4.shared.b16 {%0,%1,%2,%3}, [%4];"
                 : "=r"(r[0]), "=r"(r[1]), "=r"(r[2]), "=r"(r[3]) : "r"(addr));
}

__device__ __forceinline__ void ldm_x2(uint32_t* r, uint32_t addr) {
    asm volatile("ldmatrix.sync.aligned.m8n8.x2.shared.b16 {%0,%1}, [%2];"
                 : "=r"(r[0]), "=r"(r[1]) : "r"(addr));
}

__device__ __forceinline__ void mma16816(float* c, const uint32_t* a,
                                         const uint32_t* b) {
    asm volatile(
        "mma.sync.aligned.m16n8k16.row.col.f32.bf16.bf16.f32 "
        "{%0,%1,%2,%3}, {%4,%5,%6,%7}, {%8,%9}, {%0,%1,%2,%3};"
        : "+f"(c[0]), "+f"(c[1]), "+f"(c[2]), "+f"(c[3])
        : "r"(a[0]), "r"(a[1]), "r"(a[2]), "r"(a[3]), "r"(b[0]), "r"(b[1]));
}

// swizzled byte offset inside a 128-row x 32-col bf16 tile (64B rows)
// row, chunk(16B unit, 0..3)
__device__ __forceinline__ uint32_t swz(uint32_t row, uint32_t chunk) {
    return row * 64u + ((chunk ^ ((row >> 1) & 3u)) << 4);
}

// ======================= prep kernels ======================================

__global__ void nodeconv_split(const float* __restrict__ x,
                               const float* __restrict__ w,   // [4, Freal]
                               __nv_bfloat16* __restrict__ ghi,
                               __nv_bfloat16* __restrict__ glo,
                               int rows_out, int Freal, int Kpad, int in_stride)
{
    int idx = blockIdx.x * blockDim.x + threadIdx.x;
    int K4 = Kpad >> 2;
    if (idx >= rows_out * K4) return;
    int r = idx / K4;
    int c = (idx - r * K4) << 2;

    __align__(8) __nv_bfloat16 hv[4];
    __align__(8) __nv_bfloat16 lv[4];
    if (c < Freal) {
        float4 acc = make_float4(0.f, 0.f, 0.f, 0.f);
#pragma unroll
        for (int p = 0; p < 4; ++p) {
            float4 xv = *(const float4*)(x + (size_t)(4 * r + p) * in_stride + c);
            float4 wv = *(const float4*)(w + (size_t)p * Freal + c);
            acc.x = fmaf(xv.x, wv.x, acc.x);
            acc.y = fmaf(xv.y, wv.y, acc.y);
            acc.z = fmaf(xv.z, wv.z, acc.z);
            acc.w = fmaf(xv.w, wv.w, acc.w);
        }
        float s[4] = {acc.x, acc.y, acc.z, acc.w};
#pragma unroll
        for (int i = 0; i < 4; ++i) {
            hv[i] = __float2bfloat16(s[i]);
            lv[i] = __float2bfloat16(s[i] - __bfloat162float(hv[i]));
        }
    } else {
#pragma unroll
        for (int i = 0; i < 4; ++i) {
            hv[i] = __float2bfloat16(0.f);
            lv[i] = __float2bfloat16(0.f);
        }
    }
    *(uint2*)(ghi + (size_t)r * Kpad + c) = *(uint2*)hv;
    *(uint2*)(glo + (size_t)r * Kpad + c) = *(uint2*)lv;
}

__global__ void transpose_split(const float* __restrict__ W,
                                __nv_bfloat16* __restrict__ bhi,
                                __nv_bfloat16* __restrict__ blo,
                                int Kreal, int Kpad, int Nreal, int Npad)
{
    __shared__ float tile[32][33];
    int nb = blockIdx.x * 32, kb = blockIdx.y * 32;
    int tx = threadIdx.x, ty = threadIdx.y;  // (32, 8)
#pragma unroll
    for (int i = 0; i < 32; i += 8) {
        int k = kb + ty + i, n = nb + tx;
        tile[ty + i][tx] = (k < Kreal && n < Nreal) ? W[(size_t)k * Nreal + n] : 0.f;
    }
    __syncthreads();
#pragma unroll
    for (int i = 0; i < 32; i += 8) {
        int n = nb + ty + i, k = kb + tx;
        if (n < Npad && k < Kpad) {
            float s = tile[tx][ty + i];
            __nv_bfloat16 h = __float2bfloat16(s);
            bhi[(size_t)n * Kpad + k] = h;
            blo[(size_t)n * Kpad + k] = __float2bfloat16(s - __bfloat162float(h));
        }
    }
}

// ======================= bf16x3 mma.sync GEMM ==============================
// C[M, ostride] (valid cols < Nreal) = lrelu(A @ B^T + bias)
// A: [M,K] bf16 hi/lo row-major;  B: [Npad,K] bf16 hi/lo row-major
// grid = (Npad/128, M/128), 256 threads, K % 32 == 0, K/32 >= 4

#define BK       32
#define STAGES   4
#define TILE_B   8192                  // one 128x32 bf16 tile
#define STAGE_B  (4 * TILE_B)          // Ahi, Alo, Bhi, Blo
#define SMEM_DYN (STAGES * STAGE_B)    // 131072

__global__ __launch_bounds__(256, 1)
void gemm_bf16x3(const __nv_bfloat16* __restrict__ Ahi,
                 const __nv_bfloat16* __restrict__ Alo,
                 const __nv_bfloat16* __restrict__ Bhi,
                 const __nv_bfloat16* __restrict__ Blo,
                 const float* __restrict__ bias,
                 float* __restrict__ C,
                 int K, int Nreal, int ostride)
{
    extern __shared__ __align__(1024) char smem[];
    const uint32_t sb = smem_u32(smem);

    const int tid  = threadIdx.x;
    const int wid  = tid >> 5;
    const int lane = tid & 31;
    const int row0 = blockIdx.y * 128;
    const int col0 = blockIdx.x * 128;
    const int NC   = K / BK;

    const int warp_m = (wid & 1) * 64;        // 2 warps in M
    const int warp_n = (wid >> 1) * 32;       // 4 warps in N

    // ---- cp.async mapping: thread covers 2 chunks per 128x32 tile ----
    const int i0 = tid, i1 = tid + 256;       // chunk indices 0..511
    const int r0c = i0 >> 2, c0c = i0 & 3;
    const int r1c = i1 >> 2, c1c = i1 & 3;
    const uint32_t s0 = swz(r0c, c0c);
    const uint32_t s1 = swz(r1c, c1c);

    auto issue_stage = [&](int st, int kt) {
        const int kb = kt * BK;
        const uint32_t base = sb + st * STAGE_B;
        const size_t ga0 = (size_t)(row0 + r0c) * K + kb + c0c * 8;
        const size_t ga1 = (size_t)(row0 + r1c) * K + kb + c1c * 8;
        const size_t gb0 = (size_t)(col0 + r0c) * K + kb + c0c * 8;
        const size_t gb1 = (size_t)(col0 + r1c) * K + kb + c1c * 8;
        cp16(base + s0,              Ahi + ga0);
        cp16(base + s1,              Ahi + ga1);
        cp16(base + TILE_B + s0,     Alo + ga0);
        cp16(base + TILE_B + s1,     Alo + ga1);
        cp16(base + 2 * TILE_B + s0, Bhi + gb0);
        cp16(base + 2 * TILE_B + s1, Bhi + gb1);
        cp16(base + 3 * TILE_B + s0, Blo + gb0);
        cp16(base + 3 * TILE_B + s1, Blo + gb1);
        asm volatile("cp.async.commit_group;");
    };

    float acc[4][4][4];
#pragma unroll
    for (int mt = 0; mt < 4; ++mt)
#pragma unroll
        for (int nt = 0; nt < 4; ++nt)
#pragma unroll
            for (int q = 0; q < 4; ++q) acc[mt][nt][q] = 0.f;

    // prologue: stages 0..2
    issue_stage(0, 0);
    issue_stage(1, 1);
    issue_stage(2, 2);

    // ldmatrix lane-dependent pieces
    const uint32_t a_lrow = lane & 15;          // + warp_m + 16*mt
    const uint32_t a_lchk = lane >> 4;          // + 2*ks
    const uint32_t b_lrow = lane & 7;           // + warp_n + 8*nt
    const uint32_t b_lchk = (lane >> 3) & 1;    // + 2*ks

    for (int i = 0; i < NC; ++i) {
        asm volatile("cp.async.wait_group 2;");
        __syncthreads();
        if (i + 3 < NC) issue_stage((i + 3) & 3, i + 3);

        const uint32_t base = sb + (i & 3) * STAGE_B;
#pragma unroll
        for (int ks = 0; ks < 2; ++ks) {
            uint32_t ahi[4][4], alo[4][4], bhi[4][2], blo[4][2];
#pragma unroll
            for (int mt = 0; mt < 4; ++mt) {
                const uint32_t off =
                    swz(warp_m + mt * 16 + a_lrow, ks * 2 + a_lchk);
                ldm_x4(ahi[mt], base + off);
                ldm_x4(alo[mt], base + TILE_B + off);
            }
#pragma unroll
            for (int nt = 0; nt < 4; ++nt) {
                const uint32_t off =
                    swz(warp_n + nt * 8 + b_lrow, ks * 2 + b_lchk);
                ldm_x2(bhi[nt], base + 2 * TILE_B + off);
                ldm_x2(blo[nt], base + 3 * TILE_B + off);
            }
#pragma unroll
            for (int mt = 0; mt < 4; ++mt)
#pragma unroll
                for (int nt = 0; nt < 4; ++nt) {
                    mma16816(acc[mt][nt], ahi[mt], bhi[nt]);
                    mma16816(acc[mt][nt], ahi[mt], blo[nt]);
                    mma16816(acc[mt][nt], alo[mt], bhi[nt]);
                }
        }
        __syncthreads();
    }

    // ---- epilogue: bias + leaky relu ----
    const int erow = lane >> 2;
    const int ecol = (lane & 3) * 2;
#pragma unroll
    for (int mt = 0; mt < 4; ++mt) {
#pragma unroll
        for (int nt = 0; nt < 4; ++nt) {
            const int colg = col0 + warp_n + nt * 8 + ecol;
            if (colg >= Nreal) continue;
            const float bx = bias[colg], by = bias[colg + 1];
            const int rg0 = row0 + warp_m + mt * 16 + erow;
            float v0 = acc[mt][nt][0] + bx;
            float v1 = acc[mt][nt][1] + by;
            float v2 = acc[mt][nt][2] + bx;
            float v3 = acc[mt][nt][3] + by;
            v0 = (v0 >= 0.f) ? v0 : 0.01f * v0;
            v1 = (v1 >= 0.f) ? v1 : 0.01f * v1;
            v2 = (v2 >= 0.f) ? v2 : 0.01f * v2;
            v3 = (v3 >= 0.f) ? v3 : 0.01f * v3;
            *(float2*)(C + (size_t)rg0 * ostride + colg) =
                make_float2(v0, v1);
            *(float2*)(C + (size_t)(rg0 + 8) * ostride + colg) =
                make_float2(v2, v3);
        }
    }
}

// ======================= launch ============================================

extern "C" void kernel_launch(void* const* d_in, const int* in_sizes, int n_in,
                              void* d_out, int out_size)
{
    const float* x       = (const float*)d_in[0];   // [64,512,2048]
    const float* conv1_w = (const float*)d_in[1];   // [4,2048]
    const float* prop1_W = (const float*)d_in[4];   // [2048,1100]
    const float* prop1_B = (const float*)d_in[5];   // [1100]
    const float* conv2_w = (const float*)d_in[6];   // [4,1100]
    const float* prop2_W = (const float*)d_in[9];   // [1100,512]
    const float* prop2_B = (const float*)d_in[10];  // [512]

    __nv_bfloat16 *g1hi, *g1lo, *g2hi, *g2lo, *w1hi, *w1lo, *w2hi, *w2lo;
    float* h;
    cudaGetSymbolAddress((void**)&g1hi, g_g1hi);
    cudaGetSymbolAddress((void**)&g1lo, g_g1lo);
    cudaGetSymbolAddress((void**)&h,    g_h);
    cudaGetSymbolAddress((void**)&g2hi, g_g2hi);
    cudaGetSymbolAddress((void**)&g2lo, g_g2lo);
    cudaGetSymbolAddress((void**)&w1hi, g_w1hi);
    cudaGetSymbolAddress((void**)&w1lo, g_w1lo);
    cudaGetSymbolAddress((void**)&w2hi, g_w2hi);
    cudaGetSymbolAddress((void**)&w2lo, g_w2lo);

    cudaFuncSetAttribute(gemm_bf16x3,
                         cudaFuncAttributeMaxDynamicSharedMemorySize, SMEM_DYN);

    // weight transforms
    {
        dim3 blk(32, 8);
        transpose_split<<<dim3(N1P / 32, F1 / 32), blk>>>(prop1_W, w1hi, w1lo,
                                                          F1, F1, N1R, N1P);
        transpose_split<<<dim3(N2 / 32, K2P / 32), blk>>>(prop2_W, w2hi, w2lo,
                                                          N1R, K2P, N2, N2);
    }

    // stage 1
    {
        int total = ROWS1 * (F1 / 4);
        nodeconv_split<<<(total + 255) / 256, 256>>>(x, conv1_w, g1hi, g1lo,
                                                     ROWS1, F1, F1, F1);
        gemm_bf16x3<<<dim3(N1P / 128, ROWS1 / 128), 256, SMEM_DYN>>>(
            g1hi, g1lo, w1hi, w1lo, prop1_B, h, F1, N1R, N1P);
    }

    // stage 2
    {
        int total = ROWS2 * (K2P / 4);
        nodeconv_split<<<(total + 255) / 256, 256>>>(h, conv2_w, g2hi, g2lo,
                                                     ROWS2, N1R, K2P, N1P);
        gemm_bf16x3<<<dim3(N2 / 128, ROWS2 / 128), 256, SMEM_DYN>>>(
            g2hi, g2lo, w2hi, w2lo, prop2_B, (float*)d_out, K2P, N2, N2);
    }
}

// round 4
// speedup vs baseline: 4.0354x; 1.3655x over previous
#include <cuda_runtime.h>
#include <cuda_fp16.h>
#include <cstdint>

// ---------------------------------------------------------------------------
// DCGN collapses (normalized adjacency == identity) to:
//   g1 = node_conv(x, conv1_w)                [8192, 2048]
//   h  = lrelu(g1 @ prop1_W + prop1_B)        [8192, 1100]  (N pad -> 1152)
//   g2 = node_conv(h, conv2_w)                [2048, 1100]  (K pad -> 1152)
//   out= lrelu(g2 @ prop2_W + prop2_B)        [2048, 512]
// GEMM1: fp16x2 split, 2 MMAs (Ahi·B + Alo·B), B plain fp16  (err ~2e-4)
// GEMM2: fp16x2 + B-lo term (3 MMAs) — nearly free, halves stage-2 error
// mma.sync.m16n8k16.f32.f16.f16.f32 (tcgen05 PTX is blocked at sm_103 target)
// ---------------------------------------------------------------------------

#define ROWS1 8192
#define F1    2048
#define N1R   1100
#define N1P   1152
#define ROWS2 2048
#define K2P   1152
#define N2    512

__device__ __half g_g1hi[(size_t)ROWS1 * F1];
__device__ __half g_g1lo[(size_t)ROWS1 * F1];
__device__ float  g_h   [(size_t)ROWS1 * N1P];
__device__ __half g_g2hi[(size_t)ROWS2 * K2P];
__device__ __half g_g2lo[(size_t)ROWS2 * K2P];
__device__ __half g_w1hi[(size_t)N1P * F1];
__device__ __half g_w2hi[(size_t)N2 * K2P];
__device__ __half g_w2lo[(size_t)N2 * K2P];

// ===================== PTX helpers ========================

__device__ __forceinline__ uint32_t smem_u32(const void* p) {
    uint32_t a;
    asm("{ .reg .u64 t; cvta.to.shared.u64 t, %1; cvt.u32.u64 %0, t; }"
        : "=r"(a) : "l"(p));
    return a;
}

__device__ __forceinline__ void cp16(uint32_t dst, const void* src) {
    asm volatile("cp.async.cg.shared.global [%0], [%1], 16;"
                 :: "r"(dst), "l"(src));
}

__device__ __forceinline__ void ldm_x4(uint32_t* r, uint32_t addr) {
    asm volatile("ldmatrix.sync.aligned.m8n8.x4.shared.b16 {%0,%1,%2,%3}, [%4];"
                 : "=r"(r[0]), "=r"(r[1]), "=r"(r[2]), "=r"(r[3]) : "r"(addr));
}

__device__ __forceinline__ void ldm_x2(uint32_t* r, uint32_t addr) {
    asm volatile("ldmatrix.sync.aligned.m8n8.x2.shared.b16 {%0,%1}, [%2];"
                 : "=r"(r[0]), "=r"(r[1]) : "r"(addr));
}

__device__ __forceinline__ void mma16816(float* c, const uint32_t* a,
                                         const uint32_t* b) {
    asm volatile(
        "mma.sync.aligned.m16n8k16.row.col.f32.f16.f16.f32 "
        "{%0,%1,%2,%3}, {%4,%5,%6,%7}, {%8,%9}, {%0,%1,%2,%3};"
        : "+f"(c[0]), "+f"(c[1]), "+f"(c[2]), "+f"(c[3])
        : "r"(a[0]), "r"(a[1]), "r"(a[2]), "r"(a[3]), "r"(b[0]), "r"(b[1]));
}

// swizzled byte offset inside a 128-row x 32-col fp16 tile (64B rows)
__device__ __forceinline__ uint32_t swz(uint32_t row, uint32_t chunk) {
    return row * 64u + ((chunk ^ ((row >> 1) & 3u)) << 4);
}

// ======================= prep kernels ======================================

__global__ void nodeconv_split(const float* __restrict__ x,
                               const float* __restrict__ w,   // [4, Freal]
                               __half* __restrict__ ghi,
                               __half* __restrict__ glo,
                               int rows_out, int Freal, int Kpad, int in_stride)
{
    int idx = blockIdx.x * blockDim.x + threadIdx.x;
    int K4 = Kpad >> 2;
    if (idx >= rows_out * K4) return;
    int r = idx / K4;
    int c = (idx - r * K4) << 2;

    __align__(8) __half hv[4];
    __align__(8) __half lv[4];
    if (c < Freal) {
        float4 acc = make_float4(0.f, 0.f, 0.f, 0.f);
#pragma unroll
        for (int p = 0; p < 4; ++p) {
            float4 xv = *(const float4*)(x + (size_t)(4 * r + p) * in_stride + c);
            float4 wv = *(const float4*)(w + (size_t)p * Freal + c);
            acc.x = fmaf(xv.x, wv.x, acc.x);
            acc.y = fmaf(xv.y, wv.y, acc.y);
            acc.z = fmaf(xv.z, wv.z, acc.z);
            acc.w = fmaf(xv.w, wv.w, acc.w);
        }
        float s[4] = {acc.x, acc.y, acc.z, acc.w};
#pragma unroll
        for (int i = 0; i < 4; ++i) {
            hv[i] = __float2half_rn(s[i]);
            lv[i] = __float2half_rn(s[i] - __half2float(hv[i]));
        }
    } else {
#pragma unroll
        for (int i = 0; i < 4; ++i) {
            hv[i] = __float2half_rn(0.f);
            lv[i] = __float2half_rn(0.f);
        }
    }
    *(uint2*)(ghi + (size_t)r * Kpad + c) = *(uint2*)hv;
    *(uint2*)(glo + (size_t)r * Kpad + c) = *(uint2*)lv;
}

// out[n,k] = W[k,n] as fp16 hi (and optional lo), zero-padded
__global__ void transpose_split(const float* __restrict__ W,
                                __half* __restrict__ bhi,
                                __half* __restrict__ blo,   // may be null
                                int Kreal, int Kpad, int Nreal, int Npad)
{
    __shared__ float tile[32][33];
    int nb = blockIdx.x * 32, kb = blockIdx.y * 32;
    int tx = threadIdx.x, ty = threadIdx.y;  // (32, 8)
#pragma unroll
    for (int i = 0; i < 32; i += 8) {
        int k = kb + ty + i, n = nb + tx;
        tile[ty + i][tx] = (k < Kreal && n < Nreal) ? W[(size_t)k * Nreal + n] : 0.f;
    }
    __syncthreads();
#pragma unroll
    for (int i = 0; i < 32; i += 8) {
        int n = nb + ty + i, k = kb + tx;
        if (n < Npad && k < Kpad) {
            float s = tile[tx][ty + i];
            __half h = __float2half_rn(s);
            bhi[(size_t)n * Kpad + k] = h;
            if (blo)
                blo[(size_t)n * Kpad + k] = __float2half_rn(s - __half2float(h));
        }
    }
}

// ======================= fp16x2 mma.sync GEMM ==============================
// C[M, ostride] (valid cols < Nreal) = lrelu(A @ B^T + bias)
// NB = 1: acc = Ahi·Bhi + Alo·Bhi           (stage-1; 2 MMAs)
// NB = 2: acc = Ahi·Bhi + Alo·Bhi + Ahi·Blo (stage-2; 3 MMAs)
// grid = (Npad/128, M/128), 256 threads, K % 32 == 0, K/32 >= 4

#define BK       32
#define STAGES   4
#define TILE_B   8192                  // one 128x32 fp16 tile

template <int NB>
__global__ __launch_bounds__(256, NB == 1 ? 2 : 1)
void gemm_fp16(const __half* __restrict__ Ahi,
               const __half* __restrict__ Alo,
               const __half* __restrict__ Bhi,
               const __half* __restrict__ Blo,
               const float* __restrict__ bias,
               float* __restrict__ C,
               int K, int Nreal, int ostride)
{
    constexpr int NT = 2 + NB;                 // tiles per stage
    constexpr int STAGE_B = NT * TILE_B;

    extern __shared__ __align__(1024) char smem[];
    const uint32_t sb = smem_u32(smem);

    const int tid  = threadIdx.x;
    const int wid  = tid >> 5;
    const int lane = tid & 31;
    const int row0 = blockIdx.y * 128;
    const int col0 = blockIdx.x * 128;
    const int NC   = K / BK;

    const int warp_m = (wid & 1) * 64;        // 2 warps in M
    const int warp_n = (wid >> 1) * 32;       // 4 warps in N

    // ---- cp.async mapping: thread covers 2 chunks per 128x32 tile ----
    const int i0 = tid, i1 = tid + 256;
    const int r0c = i0 >> 2, c0c = i0 & 3;
    const int r1c = i1 >> 2, c1c = i1 & 3;
    const uint32_t s0 = swz(r0c, c0c);
    const uint32_t s1 = swz(r1c, c1c);

    auto issue_stage = [&](int st, int kt) {
        const int kb = kt * BK;
        const uint32_t base = sb + st * STAGE_B;
        const size_t ga0 = (size_t)(row0 + r0c) * K + kb + c0c * 8;
        const size_t ga1 = (size_t)(row0 + r1c) * K + kb + c1c * 8;
        const size_t gb0 = (size_t)(col0 + r0c) * K + kb + c0c * 8;
        const size_t gb1 = (size_t)(col0 + r1c) * K + kb + c1c * 8;
        cp16(base + s0,              Ahi + ga0);
        cp16(base + s1,              Ahi + ga1);
        cp16(base + TILE_B + s0,     Alo + ga0);
        cp16(base + TILE_B + s1,     Alo + ga1);
        cp16(base + 2 * TILE_B + s0, Bhi + gb0);
        cp16(base + 2 * TILE_B + s1, Bhi + gb1);
        if (NB == 2) {
            cp16(base + 3 * TILE_B + s0, Blo + gb0);
            cp16(base + 3 * TILE_B + s1, Blo + gb1);
        }
        asm volatile("cp.async.commit_group;");
    };

    float acc[4][4][4];
#pragma unroll
    for (int mt = 0; mt < 4; ++mt)
#pragma unroll
        for (int nt = 0; nt < 4; ++nt)
#pragma unroll
            for (int q = 0; q < 4; ++q) acc[mt][nt][q] = 0.f;

    issue_stage(0, 0);
    issue_stage(1, 1);
    issue_stage(2, 2);

    const uint32_t a_lrow = lane & 15;
    const uint32_t a_lchk = lane >> 4;
    const uint32_t b_lrow = lane & 7;
    const uint32_t b_lchk = (lane >> 3) & 1;

    for (int i = 0; i < NC; ++i) {
        asm volatile("cp.async.wait_group 2;");
        __syncthreads();
        if (i + 3 < NC) issue_stage((i + 3) & 3, i + 3);

        const uint32_t base = sb + (i & 3) * STAGE_B;
#pragma unroll
        for (int ks = 0; ks < 2; ++ks) {
            uint32_t bhi[4][2], blo[4][2];
#pragma unroll
            for (int nt = 0; nt < 4; ++nt) {
                const uint32_t off =
                    swz(warp_n + nt * 8 + b_lrow, ks * 2 + b_lchk);
                ldm_x2(bhi[nt], base + 2 * TILE_B + off);
                if (NB == 2) ldm_x2(blo[nt], base + 3 * TILE_B + off);
            }
#pragma unroll
            for (int mt = 0; mt < 4; ++mt) {
                uint32_t ahi[4], alo[4];
                const uint32_t off =
                    swz(warp_m + mt * 16 + a_lrow, ks * 2 + a_lchk);
                ldm_x4(ahi, base + off);
                ldm_x4(alo, base + TILE_B + off);
#pragma unroll
                for (int nt = 0; nt < 4; ++nt) {
                    mma16816(acc[mt][nt], ahi, bhi[nt]);
                    mma16816(acc[mt][nt], alo, bhi[nt]);
                    if (NB == 2) mma16816(acc[mt][nt], ahi, blo[nt]);
                }
            }
        }
        __syncthreads();
    }

    // ---- epilogue: bias + leaky relu ----
    const int erow = lane >> 2;
    const int ecol = (lane & 3) * 2;
#pragma unroll
    for (int mt = 0; mt < 4; ++mt) {
#pragma unroll
        for (int nt = 0; nt < 4; ++nt) {
            const int colg = col0 + warp_n + nt * 8 + ecol;
            if (colg >= Nreal) continue;
            const float bx = bias[colg], by = bias[colg + 1];
            const int rg0 = row0 + warp_m + mt * 16 + erow;
            float v0 = acc[mt][nt][0] + bx;
            float v1 = acc[mt][nt][1] + by;
            float v2 = acc[mt][nt][2] + bx;
            float v3 = acc[mt][nt][3] + by;
            v0 = (v0 >= 0.f) ? v0 : 0.01f * v0;
            v1 = (v1 >= 0.f) ? v1 : 0.01f * v1;
            v2 = (v2 >= 0.f) ? v2 : 0.01f * v2;
            v3 = (v3 >= 0.f) ? v3 : 0.01f * v3;
            *(float2*)(C + (size_t)rg0 * ostride + colg) =
                make_float2(v0, v1);
            *(float2*)(C + (size_t)(rg0 + 8) * ostride + colg) =
                make_float2(v2, v3);
        }
    }
}

// ======================= launch ============================================

extern "C" void kernel_launch(void* const* d_in, const int* in_sizes, int n_in,
                              void* d_out, int out_size)
{
    const float* x       = (const float*)d_in[0];   // [64,512,2048]
    const float* conv1_w = (const float*)d_in[1];   // [4,2048]
    const float* prop1_W = (const float*)d_in[4];   // [2048,1100]
    const float* prop1_B = (const float*)d_in[5];   // [1100]
    const float* conv2_w = (const float*)d_in[6];   // [4,1100]
    const float* prop2_W = (const float*)d_in[9];   // [1100,512]
    const float* prop2_B = (const float*)d_in[10];  // [512]

    __half *g1hi, *g1lo, *g2hi, *g2lo, *w1hi, *w2hi, *w2lo;
    float* h;
    cudaGetSymbolAddress((void**)&g1hi, g_g1hi);
    cudaGetSymbolAddress((void**)&g1lo, g_g1lo);
    cudaGetSymbolAddress((void**)&h,    g_h);
    cudaGetSymbolAddress((void**)&g2hi, g_g2hi);
    cudaGetSymbolAddress((void**)&g2lo, g_g2lo);
    cudaGetSymbolAddress((void**)&w1hi, g_w1hi);
    cudaGetSymbolAddress((void**)&w2hi, g_w2hi);
    cudaGetSymbolAddress((void**)&w2lo, g_w2lo);

    const int SMEM1 = STAGES * 3 * TILE_B;   // 98304
    const int SMEM2 = STAGES * 4 * TILE_B;   // 131072
    cudaFuncSetAttribute(gemm_fp16<1>,
                         cudaFuncAttributeMaxDynamicSharedMemorySize, SMEM1);
    cudaFuncSetAttribute(gemm_fp16<2>,
                         cudaFuncAttributeMaxDynamicSharedMemorySize, SMEM2);

    // weight transforms
    {
        dim3 blk(32, 8);
        transpose_split<<<dim3(N1P / 32, F1 / 32), blk>>>(
            prop1_W, w1hi, (__half*)nullptr, F1, F1, N1R, N1P);
        transpose_split<<<dim3(N2 / 32, K2P / 32), blk>>>(
            prop2_W, w2hi, w2lo, N1R, K2P, N2, N2);
    }

    // stage 1
    {
        int total = ROWS1 * (F1 / 4);
        nodeconv_split<<<(total + 255) / 256, 256>>>(x, conv1_w, g1hi, g1lo,
                                                     ROWS1, F1, F1, F1);
        gemm_fp16<1><<<dim3(N1P / 128, ROWS1 / 128), 256, SMEM1>>>(
            g1hi, g1lo, w1hi, nullptr, prop1_B, h, F1, N1R, N1P);
    }

    // stage 2
    {
        int total = ROWS2 * (K2P / 4);
        nodeconv_split<<<(total + 255) / 256, 256>>>(h, conv2_w, g2hi, g2lo,
                                                     ROWS2, N1R, K2P, N1P);
        gemm_fp16<2><<<dim3(N2 / 128, ROWS2 / 128), 256, SMEM2>>>(
            g2hi, g2lo, w2hi, w2lo, prop2_B, (float*)d_out, K2P, N2, N2);
    }
}

// round 5
// speedup vs baseline: 5.7207x; 1.4176x over previous
#include <cuda_runtime.h>
#include <cuda_fp16.h>
#include <cstdint>

// ---------------------------------------------------------------------------
// DCGN collapses (normalized adjacency == identity) to:
//   g1 = node_conv(x, conv1_w)                [8192, 2048]
//   h  = lrelu(g1 @ prop1_W + prop1_B)        [8192, 1100]  (N pad -> 1152)
//   g2 = node_conv(h, conv2_w)                [2048, 1100]  (K pad -> 1152)
//   out= lrelu(g2 @ prop2_W + prop2_B)        [2048, 512]
// GEMM1: plain fp16 x fp16, 1 MMA  (measured-error model says ~2-3e-5)
// GEMM2: fp16x2 split both sides, 3 MMAs (near-free, anchors total error)
// ---------------------------------------------------------------------------

#define ROWS1 8192
#define F1    2048
#define N1R   1100
#define N1P   1152
#define ROWS2 2048
#define K2P   1152
#define N2    512

__device__ __half g_g1hi[(size_t)ROWS1 * F1];
__device__ float  g_h   [(size_t)ROWS1 * N1P];
__device__ __half g_g2hi[(size_t)ROWS2 * K2P];
__device__ __half g_g2lo[(size_t)ROWS2 * K2P];
__device__ __half g_w1hi[(size_t)N1P * F1];
__device__ __half g_w2hi[(size_t)N2 * K2P];
__device__ __half g_w2lo[(size_t)N2 * K2P];

// ===================== PTX helpers ========================

__device__ __forceinline__ uint32_t smem_u32(const void* p) {
    uint32_t a;
    asm("{ .reg .u64 t; cvta.to.shared.u64 t, %1; cvt.u32.u64 %0, t; }"
        : "=r"(a) : "l"(p));
    return a;
}

__device__ __forceinline__ void cp16(uint32_t dst, const void* src) {
    asm volatile("cp.async.cg.shared.global [%0], [%1], 16;"
                 :: "r"(dst), "l"(src));
}

__device__ __forceinline__ void ldm_x4(uint32_t* r, uint32_t addr) {
    asm volatile("ldmatrix.sync.aligned.m8n8.x4.shared.b16 {%0,%1,%2,%3}, [%4];"
                 : "=r"(r[0]), "=r"(r[1]), "=r"(r[2]), "=r"(r[3]) : "r"(addr));
}

__device__ __forceinline__ void ldm_x2(uint32_t* r, uint32_t addr) {
    asm volatile("ldmatrix.sync.aligned.m8n8.x2.shared.b16 {%0,%1}, [%2];"
                 : "=r"(r[0]), "=r"(r[1]) : "r"(addr));
}

__device__ __forceinline__ void mma16816(float* c, const uint32_t* a,
                                         const uint32_t* b) {
    asm volatile(
        "mma.sync.aligned.m16n8k16.row.col.f32.f16.f16.f32 "
        "{%0,%1,%2,%3}, {%4,%5,%6,%7}, {%8,%9}, {%0,%1,%2,%3};"
        : "+f"(c[0]), "+f"(c[1]), "+f"(c[2]), "+f"(c[3])
        : "r"(a[0]), "r"(a[1]), "r"(a[2]), "r"(a[3]), "r"(b[0]), "r"(b[1]));
}

// swizzled byte offset inside a 128-row x 32-col fp16 tile (64B rows)
__device__ __forceinline__ uint32_t swz(uint32_t row, uint32_t chunk) {
    return row * 64u + ((chunk ^ ((row >> 1) & 3u)) << 4);
}

// ======================= prep kernels ======================================

// ghi (+ optional glo) = fp16 split of node_conv(x, w), zero-padded to Kpad
__global__ void nodeconv_split(const float* __restrict__ x,
                               const float* __restrict__ w,   // [4, Freal]
                               __half* __restrict__ ghi,
                               __half* __restrict__ glo,      // may be null
                               int rows_out, int Freal, int Kpad, int in_stride)
{
    int idx = blockIdx.x * blockDim.x + threadIdx.x;
    int K4 = Kpad >> 2;
    if (idx >= rows_out * K4) return;
    int r = idx / K4;
    int c = (idx - r * K4) << 2;

    __align__(8) __half hv[4];
    __align__(8) __half lv[4];
    if (c < Freal) {
        float4 acc = make_float4(0.f, 0.f, 0.f, 0.f);
#pragma unroll
        for (int p = 0; p < 4; ++p) {
            float4 xv = *(const float4*)(x + (size_t)(4 * r + p) * in_stride + c);
            float4 wv = *(const float4*)(w + (size_t)p * Freal + c);
            acc.x = fmaf(xv.x, wv.x, acc.x);
            acc.y = fmaf(xv.y, wv.y, acc.y);
            acc.z = fmaf(xv.z, wv.z, acc.z);
            acc.w = fmaf(xv.w, wv.w, acc.w);
        }
        float s[4] = {acc.x, acc.y, acc.z, acc.w};
#pragma unroll
        for (int i = 0; i < 4; ++i) {
            hv[i] = __float2half_rn(s[i]);
            lv[i] = __float2half_rn(s[i] - __half2float(hv[i]));
        }
    } else {
#pragma unroll
        for (int i = 0; i < 4; ++i) {
            hv[i] = __float2half_rn(0.f);
            lv[i] = __float2half_rn(0.f);
        }
    }
    *(uint2*)(ghi + (size_t)r * Kpad + c) = *(uint2*)hv;
    if (glo) *(uint2*)(glo + (size_t)r * Kpad + c) = *(uint2*)lv;
}

// out[n,k] = W[k,n] as fp16 hi (and optional lo), zero-padded
__global__ void transpose_split(const float* __restrict__ W,
                                __half* __restrict__ bhi,
                                __half* __restrict__ blo,   // may be null
                                int Kreal, int Kpad, int Nreal, int Npad)
{
    __shared__ float tile[32][33];
    int nb = blockIdx.x * 32, kb = blockIdx.y * 32;
    int tx = threadIdx.x, ty = threadIdx.y;  // (32, 8)
#pragma unroll
    for (int i = 0; i < 32; i += 8) {
        int k = kb + ty + i, n = nb + tx;
        tile[ty + i][tx] = (k < Kreal && n < Nreal) ? W[(size_t)k * Nreal + n] : 0.f;
    }
    __syncthreads();
#pragma unroll
    for (int i = 0; i < 32; i += 8) {
        int n = nb + ty + i, k = kb + tx;
        if (n < Npad && k < Kpad) {
            float s = tile[tx][ty + i];
            __half h = __float2half_rn(s);
            bhi[(size_t)n * Kpad + k] = h;
            if (blo)
                blo[(size_t)n * Kpad + k] = __float2half_rn(s - __half2float(h));
        }
    }
}

// ======================= fp16 mma.sync GEMM ================================
// C[M, ostride] (valid cols < Nreal) = lrelu(A @ B^T + bias)
// ALO=0,BLO=0: acc = A·B                           (1 MMA)
// ALO=1,BLO=1: acc = Ahi·Bhi + Alo·Bhi + Ahi·Blo   (3 MMAs)
// grid = (Npad/128, M/128), 256 threads, K % 32 == 0, K/32 >= 4

#define BK       32
#define STAGES   4
#define TILE_B   8192                  // one 128x32 fp16 tile

template <bool ALO, bool BLO>
__global__ __launch_bounds__(256, (ALO || BLO) ? 1 : 2)
void gemm_fp16(const __half* __restrict__ Ahi,
               const __half* __restrict__ Alo,
               const __half* __restrict__ Bhi,
               const __half* __restrict__ Blo,
               const float* __restrict__ bias,
               float* __restrict__ C,
               int K, int Nreal, int ostride)
{
    constexpr int NA = 1 + (ALO ? 1 : 0);
    constexpr int NT = NA + 1 + (BLO ? 1 : 0);
    constexpr int STAGE_B = NT * TILE_B;
    constexpr uint32_t BOFF = NA * TILE_B;

    extern __shared__ __align__(1024) char smem[];
    const uint32_t sb = smem_u32(smem);

    const int tid  = threadIdx.x;
    const int wid  = tid >> 5;
    const int lane = tid & 31;
    const int row0 = blockIdx.y * 128;
    const int col0 = blockIdx.x * 128;
    const int NC   = K / BK;

    const int warp_m = (wid & 1) * 64;        // 2 warps in M
    const int warp_n = (wid >> 1) * 32;       // 4 warps in N

    // ---- cp.async mapping: thread covers 2 chunks per 128x32 tile ----
    const int i0 = tid, i1 = tid + 256;
    const int r0c = i0 >> 2, c0c = i0 & 3;
    const int r1c = i1 >> 2, c1c = i1 & 3;
    const uint32_t s0 = swz(r0c, c0c);
    const uint32_t s1 = swz(r1c, c1c);

    auto issue_stage = [&](int st, int kt) {
        const int kb = kt * BK;
        const uint32_t base = sb + st * STAGE_B;
        const size_t ga0 = (size_t)(row0 + r0c) * K + kb + c0c * 8;
        const size_t ga1 = (size_t)(row0 + r1c) * K + kb + c1c * 8;
        const size_t gb0 = (size_t)(col0 + r0c) * K + kb + c0c * 8;
        const size_t gb1 = (size_t)(col0 + r1c) * K + kb + c1c * 8;
        cp16(base + s0, Ahi + ga0);
        cp16(base + s1, Ahi + ga1);
        if (ALO) {
            cp16(base + TILE_B + s0, Alo + ga0);
            cp16(base + TILE_B + s1, Alo + ga1);
        }
        cp16(base + BOFF + s0, Bhi + gb0);
        cp16(base + BOFF + s1, Bhi + gb1);
        if (BLO) {
            cp16(base + BOFF + TILE_B + s0, Blo + gb0);
            cp16(base + BOFF + TILE_B + s1, Blo + gb1);
        }
        asm volatile("cp.async.commit_group;");
    };

    float acc[4][4][4];
#pragma unroll
    for (int mt = 0; mt < 4; ++mt)
#pragma unroll
        for (int nt = 0; nt < 4; ++nt)
#pragma unroll
            for (int q = 0; q < 4; ++q) acc[mt][nt][q] = 0.f;

    issue_stage(0, 0);
    issue_stage(1, 1);
    issue_stage(2, 2);

    const uint32_t a_lrow = lane & 15;
    const uint32_t a_lchk = lane >> 4;
    const uint32_t b_lrow = lane & 7;
    const uint32_t b_lchk = (lane >> 3) & 1;

    for (int i = 0; i < NC; ++i) {
        asm volatile("cp.async.wait_group 2;");
        __syncthreads();
        if (i + 3 < NC) issue_stage((i + 3) & 3, i + 3);

        const uint32_t base = sb + (i & 3) * STAGE_B;
#pragma unroll
        for (int ks = 0; ks < 2; ++ks) {
            uint32_t bhi[4][2], blo[4][2];
#pragma unroll
            for (int nt = 0; nt < 4; ++nt) {
                const uint32_t off =
                    swz(warp_n + nt * 8 + b_lrow, ks * 2 + b_lchk);
                ldm_x2(bhi[nt], base + BOFF + off);
                if (BLO) ldm_x2(blo[nt], base + BOFF + TILE_B + off);
            }
#pragma unroll
            for (int mt = 0; mt < 4; ++mt) {
                uint32_t ahi[4], alo[4];
                const uint32_t off =
                    swz(warp_m + mt * 16 + a_lrow, ks * 2 + a_lchk);
                ldm_x4(ahi, base + off);
                if (ALO) ldm_x4(alo, base + TILE_B + off);
#pragma unroll
                for (int nt = 0; nt < 4; ++nt) {
                    mma16816(acc[mt][nt], ahi, bhi[nt]);
                    if (ALO) mma16816(acc[mt][nt], alo, bhi[nt]);
                    if (BLO) mma16816(acc[mt][nt], ahi, blo[nt]);
                }
            }
        }
        // NOTE: no trailing __syncthreads(); the top-of-loop barrier after
        // wait_group already orders stage reuse (writes to stage (i-1)&3 are
        // issued only after every thread finished reading it in iter i-1).
    }

    // ---- epilogue: bias + leaky relu ----
    const int erow = lane >> 2;
    const int ecol = (lane & 3) * 2;
#pragma unroll
    for (int mt = 0; mt < 4; ++mt) {
#pragma unroll
        for (int nt = 0; nt < 4; ++nt) {
            const int colg = col0 + warp_n + nt * 8 + ecol;
            if (colg >= Nreal) continue;
            const float bx = bias[colg], by = bias[colg + 1];
            const int rg0 = row0 + warp_m + mt * 16 + erow;
            float v0 = acc[mt][nt][0] + bx;
            float v1 = acc[mt][nt][1] + by;
            float v2 = acc[mt][nt][2] + bx;
            float v3 = acc[mt][nt][3] + by;
            v0 = (v0 >= 0.f) ? v0 : 0.01f * v0;
            v1 = (v1 >= 0.f) ? v1 : 0.01f * v1;
            v2 = (v2 >= 0.f) ? v2 : 0.01f * v2;
            v3 = (v3 >= 0.f) ? v3 : 0.01f * v3;
            *(float2*)(C + (size_t)rg0 * ostride + colg) =
                make_float2(v0, v1);
            *(float2*)(C + (size_t)(rg0 + 8) * ostride + colg) =
                make_float2(v2, v3);
        }
    }
}

// ======================= launch ============================================

extern "C" void kernel_launch(void* const* d_in, const int* in_sizes, int n_in,
                              void* d_out, int out_size)
{
    const float* x       = (const float*)d_in[0];   // [64,512,2048]
    const float* conv1_w = (const float*)d_in[1];   // [4,2048]
    const float* prop1_W = (const float*)d_in[4];   // [2048,1100]
    const float* prop1_B = (const float*)d_in[5];   // [1100]
    const float* conv2_w = (const float*)d_in[6];   // [4,1100]
    const float* prop2_W = (const float*)d_in[9];   // [1100,512]
    const float* prop2_B = (const float*)d_in[10];  // [512]

    __half *g1hi, *g2hi, *g2lo, *w1hi, *w2hi, *w2lo;
    float* h;
    cudaGetSymbolAddress((void**)&g1hi, g_g1hi);
    cudaGetSymbolAddress((void**)&h,    g_h);
    cudaGetSymbolAddress((void**)&g2hi, g_g2hi);
    cudaGetSymbolAddress((void**)&g2lo, g_g2lo);
    cudaGetSymbolAddress((void**)&w1hi, g_w1hi);
    cudaGetSymbolAddress((void**)&w2hi, g_w2hi);
    cudaGetSymbolAddress((void**)&w2lo, g_w2lo);

    const int SMEM1 = STAGES * 2 * TILE_B;   // 65536
    const int SMEM2 = STAGES * 4 * TILE_B;   // 131072
    cudaFuncSetAttribute((void*)gemm_fp16<false, false>,
                         cudaFuncAttributeMaxDynamicSharedMemorySize, SMEM1);
    cudaFuncSetAttribute((void*)gemm_fp16<true, true>,
                         cudaFuncAttributeMaxDynamicSharedMemorySize, SMEM2);

    // weight transforms
    {
        dim3 blk(32, 8);
        transpose_split<<<dim3(N1P / 32, F1 / 32), blk>>>(
            prop1_W, w1hi, (__half*)nullptr, F1, F1, N1R, N1P);
        transpose_split<<<dim3(N2 / 32, K2P / 32), blk>>>(
            prop2_W, w2hi, w2lo, N1R, K2P, N2, N2);
    }

    // stage 1
    {
        int total = ROWS1 * (F1 / 4);
        nodeconv_split<<<(total + 255) / 256, 256>>>(
            x, conv1_w, g1hi, (__half*)nullptr, ROWS1, F1, F1, F1);
        gemm_fp16<false, false><<<dim3(N1P / 128, ROWS1 / 128), 256, SMEM1>>>(
            g1hi, nullptr, w1hi, nullptr, prop1_B, h, F1, N1R, N1P);
    }

    // stage 2
    {
        int total = ROWS2 * (K2P / 4);
        nodeconv_split<<<(total + 255) / 256, 256>>>(
            h, conv2_w, g2hi, g2lo, ROWS2, N1R, K2P, N1P);
        gemm_fp16<true, true><<<dim3(N2 / 128, ROWS2 / 128), 256, SMEM2>>>(
            g2hi, g2lo, w2hi, w2lo, prop2_B, (float*)d_out, K2P, N2, N2);
    }
}

// round 6
// speedup vs baseline: 6.6904x; 1.1695x over previous
#include <cuda_runtime.h>
#include <cuda_fp16.h>
#include <cstdint>

// ---------------------------------------------------------------------------
// DCGN collapses (normalized adjacency == identity) to:
//   g1 = node_conv(x, conv1_w)                [8192, 2048]
//   h  = lrelu(g1 @ prop1_W + prop1_B)        [8192, 1100]  (N pad -> 1152)
//   g2 = node_conv(h, conv2_w)                [2048, 1100]  (K pad -> 1152)
//   out= lrelu(g2 @ prop2_W + prop2_B)        [2048, 512]
// Both GEMMs: plain fp16 x fp16 mma.sync (measured error budget ~3e-5)
// GEMM config: 128x128 CTA, 4 warps of 64x64, 4-stage cp.async, 2 CTA/SM
// ---------------------------------------------------------------------------

#define ROWS1 8192
#define F1    2048
#define N1R   1100
#define N1P   1152
#define ROWS2 2048
#define K2P   1152
#define N2    512

__device__ __half g_g1[(size_t)ROWS1 * F1];
__device__ float  g_h [(size_t)ROWS1 * N1P];
__device__ __half g_g2[(size_t)ROWS2 * K2P];
__device__ __half g_w1[(size_t)N1P * F1];
__device__ __half g_w2[(size_t)N2 * K2P];

// ===================== PTX helpers ========================

__device__ __forceinline__ uint32_t smem_u32(const void* p) {
    uint32_t a;
    asm("{ .reg .u64 t; cvta.to.shared.u64 t, %1; cvt.u32.u64 %0, t; }"
        : "=r"(a) : "l"(p));
    return a;
}

__device__ __forceinline__ void cp16(uint32_t dst, const void* src) {
    asm volatile("cp.async.cg.shared.global [%0], [%1], 16;"
                 :: "r"(dst), "l"(src));
}

__device__ __forceinline__ void ldm_x4(uint32_t* r, uint32_t addr) {
    asm volatile("ldmatrix.sync.aligned.m8n8.x4.shared.b16 {%0,%1,%2,%3}, [%4];"
                 : "=r"(r[0]), "=r"(r[1]), "=r"(r[2]), "=r"(r[3]) : "r"(addr));
}

__device__ __forceinline__ void mma16816(float* c, const uint32_t* a,
                                         const uint32_t* b) {
    asm volatile(
        "mma.sync.aligned.m16n8k16.row.col.f32.f16.f16.f32 "
        "{%0,%1,%2,%3}, {%4,%5,%6,%7}, {%8,%9}, {%0,%1,%2,%3};"
        : "+f"(c[0]), "+f"(c[1]), "+f"(c[2]), "+f"(c[3])
        : "r"(a[0]), "r"(a[1]), "r"(a[2]), "r"(a[3]), "r"(b[0]), "r"(b[1]));
}

// swizzled byte offset inside a 128-row x 32-col fp16 tile (64B rows)
__device__ __forceinline__ uint32_t swz(uint32_t row, uint32_t chunk) {
    return row * 64u + ((chunk ^ ((row >> 1) & 3u)) << 4);
}

// ======================= prep kernels ======================================

// g = fp16(node_conv(x, w)), zero-padded to Kpad columns
__global__ void nodeconv_fp16(const float* __restrict__ x,
                              const float* __restrict__ w,   // [4, Freal]
                              __half* __restrict__ g,
                              int rows_out, int Freal, int Kpad, int in_stride)
{
    int idx = blockIdx.x * blockDim.x + threadIdx.x;
    int K4 = Kpad >> 2;
    if (idx >= rows_out * K4) return;
    int r = idx / K4;
    int c = (idx - r * K4) << 2;

    __align__(8) __half hv[4];
    if (c < Freal) {
        float4 acc = make_float4(0.f, 0.f, 0.f, 0.f);
#pragma unroll
        for (int p = 0; p < 4; ++p) {
            float4 xv = *(const float4*)(x + (size_t)(4 * r + p) * in_stride + c);
            float4 wv = *(const float4*)(w + (size_t)p * Freal + c);
            acc.x = fmaf(xv.x, wv.x, acc.x);
            acc.y = fmaf(xv.y, wv.y, acc.y);
            acc.z = fmaf(xv.z, wv.z, acc.z);
            acc.w = fmaf(xv.w, wv.w, acc.w);
        }
        hv[0] = __float2half_rn(acc.x);
        hv[1] = __float2half_rn(acc.y);
        hv[2] = __float2half_rn(acc.z);
        hv[3] = __float2half_rn(acc.w);
    } else {
#pragma unroll
        for (int i = 0; i < 4; ++i) hv[i] = __float2half_rn(0.f);
    }
    *(uint2*)(g + (size_t)r * Kpad + c) = *(uint2*)hv;
}

// out[n,k] = fp16(W[k,n]), zero-padded
__global__ void transpose_fp16(const float* __restrict__ W,
                               __half* __restrict__ B,
                               int Kreal, int Kpad, int Nreal, int Npad)
{
    __shared__ float tile[32][33];
    int nb = blockIdx.x * 32, kb = blockIdx.y * 32;
    int tx = threadIdx.x, ty = threadIdx.y;  // (32, 8)
#pragma unroll
    for (int i = 0; i < 32; i += 8) {
        int k = kb + ty + i, n = nb + tx;
        tile[ty + i][tx] = (k < Kreal && n < Nreal) ? W[(size_t)k * Nreal + n] : 0.f;
    }
    __syncthreads();
#pragma unroll
    for (int i = 0; i < 32; i += 8) {
        int n = nb + ty + i, k = kb + tx;
        if (n < Npad && k < Kpad)
            B[(size_t)n * Kpad + k] = __float2half_rn(tile[tx][ty + i]);
    }
}

// ======================= fp16 mma.sync GEMM ================================
// C[M, ostride] (valid cols < Nreal) = lrelu(A @ B^T + bias)
// grid = (Npad/128, M/128), 128 threads (4 warps of 64x64), K % 32 == 0,
// K/32 >= 4.

#define BK       32
#define STAGES   4
#define TILE_B   8192                   // one 128x32 fp16 tile
#define STAGE_B  (2 * TILE_B)           // A + B
#define SMEM_DYN (STAGES * STAGE_B)     // 65536

__global__ __launch_bounds__(128, 2)
void gemm_fp16(const __half* __restrict__ A,
               const __half* __restrict__ B,
               const float* __restrict__ bias,
               float* __restrict__ C,
               int K, int Nreal, int ostride)
{
    extern __shared__ __align__(1024) char smem[];
    const uint32_t sb = smem_u32(smem);

    const int tid  = threadIdx.x;
    const int wid  = tid >> 5;
    const int lane = tid & 31;
    const int row0 = blockIdx.y * 128;
    const int col0 = blockIdx.x * 128;
    const int NC   = K / BK;

    const int warp_m = (wid & 1) * 64;     // 2 warps in M
    const int warp_n = (wid >> 1) * 64;    // 2 warps in N

    // ---- cp.async mapping: thread covers 4 chunks per 128x32 tile ----
    uint32_t ssw[4];
    int      srow[4];
#pragma unroll
    for (int q = 0; q < 4; ++q) {
        const int idx = tid + q * 128;      // 0..511
        srow[q] = idx >> 2;
        ssw[q]  = swz(idx >> 2, idx & 3);
    }
    const int schk = tid & 3;

    auto issue_stage = [&](int st, int kt) {
        const int kb = kt * BK + schk * 8;
        const uint32_t base = sb + st * STAGE_B;
#pragma unroll
        for (int q = 0; q < 4; ++q) {
            cp16(base + ssw[q],          A + (size_t)(row0 + srow[q]) * K + kb);
            cp16(base + TILE_B + ssw[q], B + (size_t)(col0 + srow[q]) * K + kb);
        }
        asm volatile("cp.async.commit_group;");
    };

    float acc[4][8][4];
#pragma unroll
    for (int mt = 0; mt < 4; ++mt)
#pragma unroll
        for (int nt = 0; nt < 8; ++nt)
#pragma unroll
            for (int q = 0; q < 4; ++q) acc[mt][nt][q] = 0.f;

    issue_stage(0, 0);
    issue_stage(1, 1);
    issue_stage(2, 2);

    // ldmatrix lane-dependent pieces
    const uint32_t a_lrow = lane & 15;              // A: 16 rows, 2 chunks
    const uint32_t a_lchk = lane >> 4;
    const uint32_t b_lrow = (lane & 7) + ((lane >> 4) << 3);   // B pairs
    const uint32_t b_lchk = (lane >> 3) & 1;

    for (int i = 0; i < NC; ++i) {
        asm volatile("cp.async.wait_group 2;");
        __syncthreads();
        if (i + 3 < NC) issue_stage((i + 3) & 3, i + 3);

        const uint32_t base = sb + (i & 3) * STAGE_B;
#pragma unroll
        for (int ks = 0; ks < 2; ++ks) {
            uint32_t bfr[8][2];
#pragma unroll
            for (int ntp = 0; ntp < 4; ++ntp) {     // 2 n-tiles per ldmatrix
                const uint32_t off =
                    swz(warp_n + ntp * 16 + b_lrow, ks * 2 + b_lchk);
                ldm_x4(&bfr[ntp * 2][0], base + TILE_B + off);
            }
#pragma unroll
            for (int mt = 0; mt < 4; ++mt) {
                uint32_t afr[4];
                const uint32_t off =
                    swz(warp_m + mt * 16 + a_lrow, ks * 2 + a_lchk);
                ldm_x4(afr, base + off);
#pragma unroll
                for (int nt = 0; nt < 8; ++nt)
                    mma16816(acc[mt][nt], afr, bfr[nt]);
            }
        }
        // stage-reuse ordering is provided by the top-of-loop barrier
    }

    // ---- epilogue: bias + leaky relu ----
    const int erow = lane >> 2;
    const int ecol = (lane & 3) * 2;
#pragma unroll
    for (int mt = 0; mt < 4; ++mt) {
#pragma unroll
        for (int nt = 0; nt < 8; ++nt) {
            const int colg = col0 + warp_n + nt * 8 + ecol;
            if (colg >= Nreal) continue;
            const float bx = bias[colg], by = bias[colg + 1];
            const int rg0 = row0 + warp_m + mt * 16 + erow;
            float v0 = acc[mt][nt][0] + bx;
            float v1 = acc[mt][nt][1] + by;
            float v2 = acc[mt][nt][2] + bx;
            float v3 = acc[mt][nt][3] + by;
            v0 = (v0 >= 0.f) ? v0 : 0.01f * v0;
            v1 = (v1 >= 0.f) ? v1 : 0.01f * v1;
            v2 = (v2 >= 0.f) ? v2 : 0.01f * v2;
            v3 = (v3 >= 0.f) ? v3 : 0.01f * v3;
            *(float2*)(C + (size_t)rg0 * ostride + colg) =
                make_float2(v0, v1);
            *(float2*)(C + (size_t)(rg0 + 8) * ostride + colg) =
                make_float2(v2, v3);
        }
    }
}

// ======================= launch ============================================

extern "C" void kernel_launch(void* const* d_in, const int* in_sizes, int n_in,
                              void* d_out, int out_size)
{
    const float* x       = (const float*)d_in[0];   // [64,512,2048]
    const float* conv1_w = (const float*)d_in[1];   // [4,2048]
    const float* prop1_W = (const float*)d_in[4];   // [2048,1100]
    const float* prop1_B = (const float*)d_in[5];   // [1100]
    const float* conv2_w = (const float*)d_in[6];   // [4,1100]
    const float* prop2_W = (const float*)d_in[9];   // [1100,512]
    const float* prop2_B = (const float*)d_in[10];  // [512]

    __half *g1, *g2, *w1, *w2;
    float* h;
    cudaGetSymbolAddress((void**)&g1, g_g1);
    cudaGetSymbolAddress((void**)&h,  g_h);
    cudaGetSymbolAddress((void**)&g2, g_g2);
    cudaGetSymbolAddress((void**)&w1, g_w1);
    cudaGetSymbolAddress((void**)&w2, g_w2);

    cudaFuncSetAttribute((void*)gemm_fp16,
                         cudaFuncAttributeMaxDynamicSharedMemorySize, SMEM_DYN);

    // weight transforms
    {
        dim3 blk(32, 8);
        transpose_fp16<<<dim3(N1P / 32, F1 / 32), blk>>>(prop1_W, w1,
                                                         F1, F1, N1R, N1P);
        transpose_fp16<<<dim3(N2 / 32, K2P / 32), blk>>>(prop2_W, w2,
                                                         N1R, K2P, N2, N2);
    }

    // stage 1
    {
        int total = ROWS1 * (F1 / 4);
        nodeconv_fp16<<<(total + 255) / 256, 256>>>(x, conv1_w, g1,
                                                    ROWS1, F1, F1, F1);
        gemm_fp16<<<dim3(N1P / 128, ROWS1 / 128), 128, SMEM_DYN>>>(
            g1, w1, prop1_B, h, F1, N1R, N1P);
    }

    // stage 2
    {
        int total = ROWS2 * (K2P / 4);
        nodeconv_fp16<<<(total + 255) / 256, 256>>>(h, conv2_w, g2,
                                                    ROWS2, N1R, K2P, N1P);
        gemm_fp16<<<dim3(N2 / 128, ROWS2 / 128), 128, SMEM_DYN>>>(
            g2, w2, prop2_B, (float*)d_out, K2P, N2, N2);
    }
}

// round 7
// speedup vs baseline: 6.8373x; 1.0220x over previous
#include <cuda_runtime.h>
#include <cuda_fp16.h>
#include <cstdint>

// ---------------------------------------------------------------------------
// DCGN collapses (normalized adjacency == identity) to:
//   g1 = node_conv(x, conv1_w)                [8192, 2048]
//   h  = lrelu(g1 @ prop1_W + prop1_B)        [8192, 1100]  (N pad -> 1152, fp16)
//   g2 = node_conv(h, conv2_w)                [2048, 1100]  (K pad -> 1152)
//   out= lrelu(g2 @ prop2_W + prop2_B)        [2048, 512]
// Both GEMMs: plain fp16 x fp16 mma.sync (measured error budget ~4e-5)
// GEMM config: 128x128 CTA, 4 warps of 64x64, BK=64, 3-stage cp.async,
// SW128 swizzle, 2 CTA/SM.
// ---------------------------------------------------------------------------

#define ROWS1 8192
#define F1    2048
#define N1R   1100
#define N1P   1152
#define ROWS2 2048
#define K2P   1152
#define N2    512

__device__ __half g_g1[(size_t)ROWS1 * F1];
__device__ __half g_h [(size_t)ROWS1 * N1P];
__device__ __half g_g2[(size_t)ROWS2 * K2P];
__device__ __half g_w1[(size_t)N1P * F1];
__device__ __half g_w2[(size_t)N2 * K2P];

// ===================== PTX helpers ========================

__device__ __forceinline__ uint32_t smem_u32(const void* p) {
    uint32_t a;
    asm("{ .reg .u64 t; cvta.to.shared.u64 t, %1; cvt.u32.u64 %0, t; }"
        : "=r"(a) : "l"(p));
    return a;
}

__device__ __forceinline__ void cp16(uint32_t dst, const void* src) {
    asm volatile("cp.async.cg.shared.global [%0], [%1], 16;"
                 :: "r"(dst), "l"(src));
}

__device__ __forceinline__ void ldm_x4(uint32_t* r, uint32_t addr) {
    asm volatile("ldmatrix.sync.aligned.m8n8.x4.shared.b16 {%0,%1,%2,%3}, [%4];"
                 : "=r"(r[0]), "=r"(r[1]), "=r"(r[2]), "=r"(r[3]) : "r"(addr));
}

__device__ __forceinline__ void mma16816(float* c, const uint32_t* a,
                                         const uint32_t* b) {
    asm volatile(
        "mma.sync.aligned.m16n8k16.row.col.f32.f16.f16.f32 "
        "{%0,%1,%2,%3}, {%4,%5,%6,%7}, {%8,%9}, {%0,%1,%2,%3};"
        : "+f"(c[0]), "+f"(c[1]), "+f"(c[2]), "+f"(c[3])
        : "r"(a[0]), "r"(a[1]), "r"(a[2]), "r"(a[3]), "r"(b[0]), "r"(b[1]));
}

// SW128 swizzled byte offset in a 128-row x 64-col fp16 tile (128B rows)
// chunk = 16B unit index 0..7
__device__ __forceinline__ uint32_t swz(uint32_t row, uint32_t chunk) {
    return row * 128u + ((chunk ^ (row & 7u)) << 4);
}

// ======================= prep kernels ======================================

// g = fp16(node_conv(x, w)), zero-padded to Kpad columns. InT = float|__half.
template <typename InT>
__global__ void nodeconv_fp16(const InT* __restrict__ x,
                              const float* __restrict__ w,   // [4, Freal]
                              __half* __restrict__ g,
                              int rows_out, int Freal, int Kpad, int in_stride)
{
    int idx = blockIdx.x * blockDim.x + threadIdx.x;
    int K4 = Kpad >> 2;
    if (idx >= rows_out * K4) return;
    int r = idx / K4;
    int c = (idx - r * K4) << 2;

    __align__(8) __half hv[4];
    if (c < Freal) {
        float acc[4] = {0.f, 0.f, 0.f, 0.f};
#pragma unroll
        for (int p = 0; p < 4; ++p) {
            float xv[4];
            if constexpr (sizeof(InT) == 4) {
                float4 t = *(const float4*)((const float*)x +
                                            (size_t)(4 * r + p) * in_stride + c);
                xv[0] = t.x; xv[1] = t.y; xv[2] = t.z; xv[3] = t.w;
            } else {
                uint2 t = *(const uint2*)((const __half*)x +
                                          (size_t)(4 * r + p) * in_stride + c);
                __half2 h0 = *(__half2*)&t.x, h1 = *(__half2*)&t.y;
                xv[0] = __low2float(h0);  xv[1] = __high2float(h0);
                xv[2] = __low2float(h1);  xv[3] = __high2float(h1);
            }
            float4 wv = *(const float4*)(w + (size_t)p * Freal + c);
            acc[0] = fmaf(xv[0], wv.x, acc[0]);
            acc[1] = fmaf(xv[1], wv.y, acc[1]);
            acc[2] = fmaf(xv[2], wv.z, acc[2]);
            acc[3] = fmaf(xv[3], wv.w, acc[3]);
        }
#pragma unroll
        for (int i = 0; i < 4; ++i) hv[i] = __float2half_rn(acc[i]);
    } else {
#pragma unroll
        for (int i = 0; i < 4; ++i) hv[i] = __float2half_rn(0.f);
    }
    *(uint2*)(g + (size_t)r * Kpad + c) = *(uint2*)hv;
}

// out[n,k] = fp16(W[k,n]), zero-padded
__global__ void transpose_fp16(const float* __restrict__ W,
                               __half* __restrict__ B,
                               int Kreal, int Kpad, int Nreal, int Npad)
{
    __shared__ float tile[32][33];
    int nb = blockIdx.x * 32, kb = blockIdx.y * 32;
    int tx = threadIdx.x, ty = threadIdx.y;  // (32, 8)
#pragma unroll
    for (int i = 0; i < 32; i += 8) {
        int k = kb + ty + i, n = nb + tx;
        tile[ty + i][tx] = (k < Kreal && n < Nreal) ? W[(size_t)k * Nreal + n] : 0.f;
    }
    __syncthreads();
#pragma unroll
    for (int i = 0; i < 32; i += 8) {
        int n = nb + ty + i, k = kb + tx;
        if (n < Npad && k < Kpad)
            B[(size_t)n * Kpad + k] = __float2half_rn(tile[tx][ty + i]);
    }
}

// ======================= fp16 mma.sync GEMM ================================
// C[M, ostride] (valid cols < Nreal) = lrelu(A @ B^T + bias)
// grid = (Npad/128, M/128), 128 threads (4 warps of 64x64), K % 64 == 0,
// K/64 >= 3. OutT = __half or float.

#define BK       64
#define STAGES   3
#define TILE_B   16384                  // one 128x64 fp16 tile
#define STAGE_B  (2 * TILE_B)           // A + B
#define SMEM_DYN (STAGES * STAGE_B)     // 98304

template <typename OutT>
__global__ __launch_bounds__(128, 2)
void gemm_fp16(const __half* __restrict__ A,
               const __half* __restrict__ B,
               const float* __restrict__ bias,
               OutT* __restrict__ C,
               int K, int Nreal, int ostride)
{
    extern __shared__ __align__(1024) char smem[];
    const uint32_t sb = smem_u32(smem);

    const int tid  = threadIdx.x;
    const int wid  = tid >> 5;
    const int lane = tid & 31;
    const int row0 = blockIdx.y * 128;
    const int col0 = blockIdx.x * 128;
    const int NC   = K / BK;

    const int warp_m = (wid & 1) * 64;     // 2 warps in M
    const int warp_n = (wid >> 1) * 64;    // 2 warps in N

    // ---- cp.async mapping: 8 chunks of 16B per thread per 128x64 tile ----
    const int srow0 = tid >> 3;            // + 16*q
    const int schk  = tid & 7;

    auto issue_stage = [&](int st, int kt) {
        const int kb = kt * BK + schk * 8;
        const uint32_t base = sb + st * STAGE_B;
#pragma unroll
        for (int q = 0; q < 8; ++q) {
            const int row = srow0 + q * 16;
            const uint32_t sw = swz(row, schk);
            cp16(base + sw,          A + (size_t)(row0 + row) * K + kb);
            cp16(base + TILE_B + sw, B + (size_t)(col0 + row) * K + kb);
        }
        asm volatile("cp.async.commit_group;");
    };

    float acc[4][8][4];
#pragma unroll
    for (int mt = 0; mt < 4; ++mt)
#pragma unroll
        for (int nt = 0; nt < 8; ++nt)
#pragma unroll
            for (int q = 0; q < 4; ++q) acc[mt][nt][q] = 0.f;

    issue_stage(0, 0);
    issue_stage(1, 1);

    // ldmatrix lane-dependent pieces
    const uint32_t a_lrow = lane & 15;                       // A rows per tile
    const uint32_t a_lchk = lane >> 4;                       // + 2*ks
    const uint32_t b_lrow = (lane & 7) + ((lane >> 4) << 3); // B row pairs
    const uint32_t b_lchk = (lane >> 3) & 1;                 // + 2*ks

    for (int i = 0; i < NC; ++i) {
        asm volatile("cp.async.wait_group 1;");
        __syncthreads();
        if (i + 2 < NC) issue_stage((i + 2) % STAGES, i + 2);

        const uint32_t base = sb + (i % STAGES) * STAGE_B;
#pragma unroll
        for (int ks = 0; ks < 4; ++ks) {
            uint32_t bfr[8][2];
#pragma unroll
            for (int ntp = 0; ntp < 4; ++ntp) {
                const uint32_t off =
                    swz(warp_n + ntp * 16 + b_lrow, ks * 2 + b_lchk);
                ldm_x4(&bfr[ntp * 2][0], base + TILE_B + off);
            }
#pragma unroll
            for (int mt = 0; mt < 4; ++mt) {
                uint32_t afr[4];
                const uint32_t off =
                    swz(warp_m + mt * 16 + a_lrow, ks * 2 + a_lchk);
                ldm_x4(afr, base + off);
#pragma unroll
                for (int nt = 0; nt < 8; ++nt)
                    mma16816(acc[mt][nt], afr, bfr[nt]);
            }
        }
        // stage-reuse ordering is provided by the top-of-loop barrier
    }

    // ---- epilogue: bias + leaky relu ----
    const int erow = lane >> 2;
    const int ecol = (lane & 3) * 2;
#pragma unroll
    for (int mt = 0; mt < 4; ++mt) {
#pragma unroll
        for (int nt = 0; nt < 8; ++nt) {
            const int colg = col0 + warp_n + nt * 8 + ecol;
            if (colg >= Nreal) continue;
            const float bx = bias[colg], by = bias[colg + 1];
            const int rg0 = row0 + warp_m + mt * 16 + erow;
            float v0 = acc[mt][nt][0] + bx;
            float v1 = acc[mt][nt][1] + by;
            float v2 = acc[mt][nt][2] + bx;
            float v3 = acc[mt][nt][3] + by;
            v0 = (v0 >= 0.f) ? v0 : 0.01f * v0;
            v1 = (v1 >= 0.f) ? v1 : 0.01f * v1;
            v2 = (v2 >= 0.f) ? v2 : 0.01f * v2;
            v3 = (v3 >= 0.f) ? v3 : 0.01f * v3;
            if constexpr (sizeof(OutT) == 2) {
                *(__half2*)((__half*)C + (size_t)rg0 * ostride + colg) =
                    __floats2half2_rn(v0, v1);
                *(__half2*)((__half*)C + (size_t)(rg0 + 8) * ostride + colg) =
                    __floats2half2_rn(v2, v3);
            } else {
                *(float2*)((float*)C + (size_t)rg0 * ostride + colg) =
                    make_float2(v0, v1);
                *(float2*)((float*)C + (size_t)(rg0 + 8) * ostride + colg) =
                    make_float2(v2, v3);
            }
        }
    }
}

// ======================= launch ============================================

extern "C" void kernel_launch(void* const* d_in, const int* in_sizes, int n_in,
                              void* d_out, int out_size)
{
    const float* x       = (const float*)d_in[0];   // [64,512,2048]
    const float* conv1_w = (const float*)d_in[1];   // [4,2048]
    const float* prop1_W = (const float*)d_in[4];   // [2048,1100]
    const float* prop1_B = (const float*)d_in[5];   // [1100]
    const float* conv2_w = (const float*)d_in[6];   // [4,1100]
    const float* prop2_W = (const float*)d_in[9];   // [1100,512]
    const float* prop2_B = (const float*)d_in[10];  // [512]

    __half *g1, *g2, *w1, *w2, *h;
    cudaGetSymbolAddress((void**)&g1, g_g1);
    cudaGetSymbolAddress((void**)&h,  g_h);
    cudaGetSymbolAddress((void**)&g2, g_g2);
    cudaGetSymbolAddress((void**)&w1, g_w1);
    cudaGetSymbolAddress((void**)&w2, g_w2);

    cudaFuncSetAttribute((void*)gemm_fp16<__half>,
                         cudaFuncAttributeMaxDynamicSharedMemorySize, SMEM_DYN);
    cudaFuncSetAttribute((void*)gemm_fp16<float>,
                         cudaFuncAttributeMaxDynamicSharedMemorySize, SMEM_DYN);

    // weight transforms
    {
        dim3 blk(32, 8);
        transpose_fp16<<<dim3(N1P / 32, F1 / 32), blk>>>(prop1_W, w1,
                                                         F1, F1, N1R, N1P);
        transpose_fp16<<<dim3(N2 / 32, K2P / 32), blk>>>(prop2_W, w2,
                                                         N1R, K2P, N2, N2);
    }

    // stage 1
    {
        int total = ROWS1 * (F1 / 4);
        nodeconv_fp16<float><<<(total + 255) / 256, 256>>>(
            x, conv1_w, g1, ROWS1, F1, F1, F1);
        gemm_fp16<__half><<<dim3(N1P / 128, ROWS1 / 128), 128, SMEM_DYN>>>(
            g1, w1, prop1_B, h, F1, N1R, N1P);
    }

    // stage 2
    {
        int total = ROWS2 * (K2P / 4);
        nodeconv_fp16<__half><<<(total + 255) / 256, 256>>>(
            h, conv2_w, g2, ROWS2, N1R, K2P, N1P);
        gemm_fp16<float><<<dim3(N2 / 128, ROWS2 / 128), 128, SMEM_DYN>>>(
            g2, w2, prop2_B, (float*)d_out, K2P, N2, N2);
    }
}